// round 14
// baseline (speedup 1.0000x reference)
#include <cuda_runtime.h>
#include <cuda_bf16.h>
#include <cstdint>
#include <math_constants.h>

#define N_  64
#define C_  8
#define L_  2048
#define S_  64
#define K_  128
#define W_  (L_ - S_ + 1)          /* 1985 */
#define WT  128                    /* windows per block */
#define NWT ((W_ + WT - 1) / WT)   /* 16 */
#define PAD 72                     /* B row pitch in bf16 (144B): conflict-free ldmatrix */
#define APITCH 48                  /* band pitch bytes, global AND smem (dense 1:1 copy) */
#define AROWS 176                  /* band rows staged per tile */
#define BROWS 2112                 /* global band rows per (n,c), zero-padded */
#define SXPAD 2128                 /* prep strip: 2048 data + 80 zero pad */
#define SQRT2F 1.41421356237f

// ---- dynamic smem (per buffer): band 8448 | B(32k) 4608 | sqx 512 ----
#define O_A      0
#define O_B      8448
#define O_SQX    13056
#define BUFSZ    13568
#define SM_MIN   27136             /* 32 int */
#define SM_TOTAL 27264

// ---------------- device scratch ----------------
__device__ __align__(16) __nv_bfloat16 g_shb[C_][K_ * PAD];            // NEGATED z-normed shapelets
__device__ __align__(16) __nv_bfloat16 g_band[N_][C_][BROWS * 24];     // Toeplitz band, pitch 48B
__device__ __align__(16) float         g_sqx[N_][C_][2048];            // window sum-of-squares

// ---------------- helpers ----------------
__device__ __forceinline__ uint32_t smem_u32(const void* p) {
    uint32_t a;
    asm("{ .reg .u64 t; cvta.to.shared.u64 t, %1; cvt.u32.u64 %0, t; }" : "=r"(a) : "l"(p));
    return a;
}
__device__ __forceinline__ float fast_sqrt(float x) {
    float r; asm("sqrt.approx.f32 %0, %1;" : "=f"(r) : "f"(x)); return r;
}
__device__ __forceinline__ void ldm4(uint32_t* r, uint32_t addr) {
    asm volatile("ldmatrix.sync.aligned.m8n8.x4.shared.b16 {%0,%1,%2,%3}, [%4];"
                 : "=r"(r[0]), "=r"(r[1]), "=r"(r[2]), "=r"(r[3]) : "r"(addr));
}
__device__ __forceinline__ void mma_bf16(float* c,
                                         const uint32_t* a, uint32_t b0, uint32_t b1) {
    asm volatile("mma.sync.aligned.m16n8k16.row.col.f32.bf16.bf16.f32 "
                 "{%0,%1,%2,%3}, {%4,%5,%6,%7}, {%8,%9}, {%0,%1,%2,%3};"
                 : "+f"(c[0]), "+f"(c[1]), "+f"(c[2]), "+f"(c[3])
                 : "r"(a[0]), "r"(a[1]), "r"(a[2]), "r"(a[3]), "r"(b0), "r"(b1));
}
__device__ __forceinline__ void cp16(uint32_t dst, const void* src) {
    asm volatile("cp.async.cg.shared.global [%0], [%1], 16;" :: "r"(dst), "l"(src));
}
__device__ __forceinline__ uint32_t bf2u(float a, float b) {
    __nv_bfloat162 v = __floats2bfloat162_rn(a, b);
    return *(uint32_t*)&v;
}

// ---------------- merged prep (576 blocks x 512 threads) ----------------
// blocks 0..511   : band + sqx for (n = b>>3, c = b&7)
// blocks 512..575 : shapelet z-norm (negated), c==0 also init out
__global__ void prep_kernel(const float* __restrict__ x, const float* __restrict__ sh,
                            float* __restrict__ out) {
    const int b = blockIdx.x, tid = threadIdx.x;
    if (b < 512) {
        const int n = b >> 3, c = b & 7;
        __shared__ float sx[SXPAD];   // 2048 data + 80 zero pad
        const float4* xr4 = (const float4*)(x + ((size_t)n * C_ + c) * L_);
        ((float4*)sx)[tid] = xr4[tid];               // 2048 floats
        if (tid < 20) ((float4*)sx)[512 + tid] = make_float4(0.f, 0.f, 0.f, 0.f);
        __syncthreads();

        // band: chunk idx -> (row = idx>>1, h = idx&1); dst = row*48 + h*16
        char* band = (char*)&g_band[n][c][0];
#pragma unroll
        for (int i = 0; i < 9; i++) {
            int idx = tid + i * 512;
            if (idx < BROWS * 2) {
                int row = idx >> 1, h = idx & 1;
                const float* p = &sx[row + 8 * h];   // max read: 2126 < SXPAD
                uint4 v;
                v.x = bf2u(p[0], p[1]); v.y = bf2u(p[2], p[3]);
                v.z = bf2u(p[4], p[5]); v.w = bf2u(p[6], p[7]);
                *(uint4*)(band + (size_t)row * APITCH + h * 16) = v;
            }
        }
        // sqx: 4 windows per thread
#pragma unroll
        for (int it = 0; it < 4; it++) {
            int w = tid + it * 512;
            float a0 = 0.f, a1 = 0.f, a2 = 0.f, a3 = 0.f;
            if (w < W_) {
                const float* src = &sx[w];
#pragma unroll
                for (int i = 0; i < 16; i++) {
                    float v0 = src[4 * i],     v1 = src[4 * i + 1];
                    float v2 = src[4 * i + 2], v3 = src[4 * i + 3];
                    a0 = fmaf(v0, v0, a0); a1 = fmaf(v1, v1, a1);
                    a2 = fmaf(v2, v2, a2); a3 = fmaf(v3, v3, a3);
                }
            }
            g_sqx[n][c][w] = (a0 + a1) + (a2 + a3);
        }
    } else {
        const int bb = b - 512;
        const int c = bb >> 3, kg = bb & 7;
        const int wid = tid >> 5, lane = tid & 31;
        const int k = kg * 16 + wid;
        const float* p = sh + ((size_t)c * K_ + k) * S_;

        float a = p[lane], bv = p[lane + 32];
        float s = a + bv;
#pragma unroll
        for (int o = 16; o > 0; o >>= 1) s += __shfl_xor_sync(0xffffffffu, s, o);
        float mu = s * (1.0f / S_);
        float da = a - mu, db = bv - mu;
        float v = da * da + db * db;
#pragma unroll
        for (int o = 16; o > 0; o >>= 1) v += __shfl_xor_sync(0xffffffffu, v, o);
        float inv = -rsqrtf(v * (1.0f / S_));    // NEGATED z-norm

        __nv_bfloat16* row = &g_shb[c][(size_t)k * PAD];
        row[lane]      = __float2bfloat16_rn(da * inv);
        row[lane + 32] = __float2bfloat16_rn(db * inv);

        if (c == 0) {
            int i = kg * 512 + tid;
            out[i] = CUDART_INF_F;
            out[i + 4096] = CUDART_INF_F;
        }
    }
}

// ---------------- main kernel ----------------
// 128 threads (4 warps). CTA tile: 128w x 32k (k-quarter = blockIdx.y).
__global__ void __launch_bounds__(128, 4)
min_dist_kernel(const float* __restrict__ x, float* __restrict__ out) {
    extern __shared__ __align__(16) char smem[];
    const int tid = threadIdx.x, wr = tid >> 5, lane = tid & 31;
    const int g = lane >> 2, q = lane & 3;
    const int kq = blockIdx.y, n = blockIdx.z, wbase = blockIdx.x * WT;

    int* s_min = (int*)(smem + SM_MIN);

    float ds[32];
#pragma unroll
    for (int i = 0; i < 32; i++) ds[i] = 0.f;

    // ---- cp.async staging: band slice + B quarter + sqx slice -> buffer buf ----
    auto stage = [&](int c, int buf) {
        uint32_t adst = smem_u32(smem) + buf * BUFSZ + O_A;
        const char* asrc = (const char*)&g_band[n][c][0] + (size_t)wbase * APITCH;
#pragma unroll
        for (int i = 0; i < 5; i++) {            // 528 chunks, dense 1:1 copy
            int idx = tid + i * 128;
            if (idx < (AROWS * APITCH) / 16) cp16(adst + idx * 16, asrc + (size_t)idx * 16);
        }
        uint32_t bdst = smem_u32(smem) + buf * BUFSZ + O_B;
        const char* bsrc = (const char*)&g_shb[c][(size_t)kq * 32 * PAD];
#pragma unroll
        for (int i = 0; i < 3; i++) {            // 288 chunks
            int idx = tid + i * 128;
            if (idx < (32 * PAD * 2) / 16) cp16(bdst + idx * 16, bsrc + (size_t)idx * 16);
        }
        if (tid < 32)
            cp16(smem_u32(smem) + buf * BUFSZ + O_SQX + tid * 16,
                 (const char*)&g_sqx[n][c][wbase] + tid * 16);
        asm volatile("cp.async.commit_group;" ::: "memory");
    };

    // ---- per-channel compute: m32n32 warp tile, diagonal A sharing ----
    // cc seeded with (sqx+S)/2; B negated -> cc_final = t/2 - cross; d = sqrt2*sqrt(|cc|)
    auto compute = [&](int buf) {
        const float* sqx = (const float*)(smem + buf * BUFSZ + O_SQX);
        uint32_t abase = smem_u32(smem) + buf * BUFSZ + O_A
                       + (uint32_t)(wr * 32 + (lane & 15)) * APITCH + (lane >> 4) * 16;
        uint32_t bbase = smem_u32(smem) + buf * BUFSZ + O_B
                       + (uint32_t)(lane & 15) * (PAD * 2) + (lane >> 4) * 16;

        uint32_t af[5][4];            // diagonal d = mi + kk, d in 0..4
#pragma unroll
        for (int d = 0; d < 5; d++)
            ldm4(af[d], abase + (uint32_t)d * 16 * APITCH);

        float th[2][2];               // 0.5*(sqx + S)
#pragma unroll
        for (int mi = 0; mi < 2; mi++) {
            th[mi][0] = fmaf(0.5f, sqx[wr * 32 + mi * 16 + g],     0.5f * (float)S_);
            th[mi][1] = fmaf(0.5f, sqx[wr * 32 + mi * 16 + g + 8], 0.5f * (float)S_);
        }

#pragma unroll
        for (int nt = 0; nt < 2; nt++) {
            uint32_t bf[4][4];
#pragma unroll
            for (int kk = 0; kk < 4; kk++)
                ldm4(bf[kk], bbase + (uint32_t)nt * 16 * (PAD * 2) + kk * 32);
            float cc[16];
#pragma unroll
            for (int mi = 0; mi < 2; mi++)
#pragma unroll
                for (int h = 0; h < 2; h++) {
                    cc[mi * 8 + h * 4 + 0] = th[mi][0];
                    cc[mi * 8 + h * 4 + 1] = th[mi][0];
                    cc[mi * 8 + h * 4 + 2] = th[mi][1];
                    cc[mi * 8 + h * 4 + 3] = th[mi][1];
                }
#pragma unroll
            for (int kk = 0; kk < 4; kk++)
#pragma unroll
                for (int mi = 0; mi < 2; mi++) {
                    mma_bf16(&cc[mi * 8],     af[mi + kk], bf[kk][0], bf[kk][2]);
                    mma_bf16(&cc[mi * 8 + 4], af[mi + kk], bf[kk][1], bf[kk][3]);
                }
#pragma unroll
            for (int e = 0; e < 16; e++) {
                float s = fast_sqrt(fabsf(cc[e]));
                ds[nt * 16 + e] = fmaf(SQRT2F, s, ds[nt * 16 + e]);
            }
        }
    };

    // ---- fully-unrolled double-buffered channel loop, ONE barrier per channel ----
    stage(0, 0);
#pragma unroll
    for (int c = 0; c < C_; c++) {
        asm volatile("cp.async.wait_group 0;" ::: "memory");
        __syncthreads();                         // data(buf) ready AND compute(c-1) done
        if (c + 1 < C_) stage(c + 1, (c + 1) & 1);
        compute(c & 1);
    }

    // ---- min over windows (32 cols for this k-quarter) ----
    __syncthreads();
    if (tid < 32) s_min[tid] = 0x7F800000;
    __syncthreads();

    bool v[2][2];
#pragma unroll
    for (int mi = 0; mi < 2; mi++)
#pragma unroll
        for (int hh = 0; hh < 2; hh++)
            v[mi][hh] = (wbase + wr * 32 + mi * 16 + g + hh * 8) < W_;

#pragma unroll
    for (int nt = 0; nt < 2; nt++)
#pragma unroll
        for (int h = 0; h < 2; h++)
#pragma unroll
            for (int j = 0; j < 2; j++) {
                float m = CUDART_INF_F;
#pragma unroll
                for (int mi = 0; mi < 2; mi++)
#pragma unroll
                    for (int hh = 0; hh < 2; hh++) {
                        float val = v[mi][hh] ? ds[nt * 16 + mi * 8 + h * 4 + hh * 2 + j]
                                              : CUDART_INF_F;
                        m = fminf(m, val);
                    }
#pragma unroll
                for (int o = 4; o < 32; o <<= 1) m = fminf(m, __shfl_xor_sync(0xffffffffu, m, o));
                if (g == 0) {
                    int col = nt * 16 + h * 8 + q * 2 + j;
                    atomicMin(&s_min[col], __float_as_int(m));
                }
            }
    __syncthreads();
    if (tid < 32) atomicMin((int*)&out[(size_t)n * K_ + kq * 32 + tid], s_min[tid]);
}

// ---------------- launch ----------------
extern "C" void kernel_launch(void* const* d_in, const int* in_sizes, int n_in,
                              void* d_out, int out_size) {
    const float* x  = (const float*)d_in[0];   // (64, 8, 2048)
    const float* sh = (const float*)d_in[1];   // (8, 128, 64)
    float* out = (float*)d_out;                // (64, 1, 128)

    cudaFuncSetAttribute(min_dist_kernel, cudaFuncAttributeMaxDynamicSharedMemorySize, SM_TOTAL);

    prep_kernel<<<576, 512>>>(x, sh, out);
    min_dist_kernel<<<dim3(NWT, 4, N_), 128, SM_TOTAL>>>(x, out);
}

// round 15
// speedup vs baseline: 1.1462x; 1.1462x over previous
#include <cuda_runtime.h>
#include <cuda_bf16.h>
#include <cstdint>
#include <math_constants.h>

#define N_  64
#define C_  8
#define L_  2048
#define S_  64
#define K_  128
#define W_  (L_ - S_ + 1)          /* 1985 */
#define WT  128                    /* windows per block */
#define NWT ((W_ + WT - 1) / WT)   /* 16 */
#define PAD 72                     /* B row pitch in bf16 (144B): conflict-free ldmatrix */
#define APITCH 48                  /* band pitch bytes, global AND smem (dense 1:1 copy) */
#define AROWS 176                  /* band rows staged per tile */
#define BROWS 2112                 /* global band rows per (n,c), zero-padded */
#define SXPAD 2128                 /* prep strip: 2048 data + 80 zero pad */
#define SQRT2F 1.41421356237f

// ---- dynamic smem (per buffer): band 8448 | B(32k) 4608 | sqx 512 ----
#define O_A      0
#define O_B      8448
#define O_SQX    13056
#define BUFSZ    13568
#define SM_MIN   27136             /* 32 int */
#define SM_TOTAL 27264

// ---------------- device scratch ----------------
__device__ __align__(16) __nv_bfloat16 g_shb[C_][K_ * PAD];            // NEGATED z-normed shapelets
__device__ __align__(16) __nv_bfloat16 g_band[N_][C_][BROWS * 24];     // Toeplitz band, pitch 48B
__device__ __align__(16) float         g_sqx[N_][C_][2048];            // window sum-of-squares

// ---------------- helpers ----------------
__device__ __forceinline__ uint32_t smem_u32(const void* p) {
    uint32_t a;
    asm("{ .reg .u64 t; cvta.to.shared.u64 t, %1; cvt.u32.u64 %0, t; }" : "=r"(a) : "l"(p));
    return a;
}
__device__ __forceinline__ float fast_sqrt(float x) {
    float r; asm("sqrt.approx.f32 %0, %1;" : "=f"(r) : "f"(x)); return r;
}
__device__ __forceinline__ void ldm4(uint32_t* r, uint32_t addr) {
    asm volatile("ldmatrix.sync.aligned.m8n8.x4.shared.b16 {%0,%1,%2,%3}, [%4];"
                 : "=r"(r[0]), "=r"(r[1]), "=r"(r[2]), "=r"(r[3]) : "r"(addr));
}
__device__ __forceinline__ void mma_bf16(float* c,
                                         const uint32_t* a, uint32_t b0, uint32_t b1) {
    asm volatile("mma.sync.aligned.m16n8k16.row.col.f32.bf16.bf16.f32 "
                 "{%0,%1,%2,%3}, {%4,%5,%6,%7}, {%8,%9}, {%0,%1,%2,%3};"
                 : "+f"(c[0]), "+f"(c[1]), "+f"(c[2]), "+f"(c[3])
                 : "r"(a[0]), "r"(a[1]), "r"(a[2]), "r"(a[3]), "r"(b0), "r"(b1));
}
__device__ __forceinline__ void cp16(uint32_t dst, const void* src) {
    asm volatile("cp.async.cg.shared.global [%0], [%1], 16;" :: "r"(dst), "l"(src));
}
__device__ __forceinline__ uint32_t bf2u(float a, float b) {
    __nv_bfloat162 v = __floats2bfloat162_rn(a, b);
    return *(uint32_t*)&v;
}

// ---------------- merged prep (576 blocks x 512 threads) ----------------
// blocks 0..511   : band + sqx for (n = b>>3, c = b&7)
// blocks 512..575 : shapelet z-norm (negated), c==0 also init out
__global__ void prep_kernel(const float* __restrict__ x, const float* __restrict__ sh,
                            float* __restrict__ out) {
    const int b = blockIdx.x, tid = threadIdx.x;
    if (b < 512) {
        const int n = b >> 3, c = b & 7;
        __shared__ float sx[SXPAD];   // 2048 data + 80 zero pad
        const float4* xr4 = (const float4*)(x + ((size_t)n * C_ + c) * L_);
        ((float4*)sx)[tid] = xr4[tid];               // 2048 floats
        if (tid < 20) ((float4*)sx)[512 + tid] = make_float4(0.f, 0.f, 0.f, 0.f);
        __syncthreads();

        // band: chunk idx -> (row = idx>>1, h = idx&1); dst = row*48 + h*16
        char* band = (char*)&g_band[n][c][0];
#pragma unroll
        for (int i = 0; i < 9; i++) {
            int idx = tid + i * 512;
            if (idx < BROWS * 2) {
                int row = idx >> 1, h = idx & 1;
                const float* p = &sx[row + 8 * h];   // max read: 2126 < SXPAD
                uint4 v;
                v.x = bf2u(p[0], p[1]); v.y = bf2u(p[2], p[3]);
                v.z = bf2u(p[4], p[5]); v.w = bf2u(p[6], p[7]);
                *(uint4*)(band + (size_t)row * APITCH + h * 16) = v;
            }
        }
        // sqx: 4 windows per thread
#pragma unroll
        for (int it = 0; it < 4; it++) {
            int w = tid + it * 512;
            float a0 = 0.f, a1 = 0.f, a2 = 0.f, a3 = 0.f;
            if (w < W_) {
                const float* src = &sx[w];
#pragma unroll
                for (int i = 0; i < 16; i++) {
                    float v0 = src[4 * i],     v1 = src[4 * i + 1];
                    float v2 = src[4 * i + 2], v3 = src[4 * i + 3];
                    a0 = fmaf(v0, v0, a0); a1 = fmaf(v1, v1, a1);
                    a2 = fmaf(v2, v2, a2); a3 = fmaf(v3, v3, a3);
                }
            }
            g_sqx[n][c][w] = (a0 + a1) + (a2 + a3);
        }
    } else {
        const int bb = b - 512;
        const int c = bb >> 3, kg = bb & 7;
        const int wid = tid >> 5, lane = tid & 31;
        const int k = kg * 16 + wid;
        const float* p = sh + ((size_t)c * K_ + k) * S_;

        float a = p[lane], bv = p[lane + 32];
        float s = a + bv;
#pragma unroll
        for (int o = 16; o > 0; o >>= 1) s += __shfl_xor_sync(0xffffffffu, s, o);
        float mu = s * (1.0f / S_);
        float da = a - mu, db = bv - mu;
        float v = da * da + db * db;
#pragma unroll
        for (int o = 16; o > 0; o >>= 1) v += __shfl_xor_sync(0xffffffffu, v, o);
        float inv = -rsqrtf(v * (1.0f / S_));    // NEGATED z-norm

        __nv_bfloat16* row = &g_shb[c][(size_t)k * PAD];
        row[lane]      = __float2bfloat16_rn(da * inv);
        row[lane + 32] = __float2bfloat16_rn(db * inv);

        if (c == 0) {
            int i = kg * 512 + tid;
            out[i] = CUDART_INF_F;
            out[i + 4096] = CUDART_INF_F;
        }
    }
}

// ---------------- main kernel ----------------
// 128 threads (4 warps). CTA tile: 128w x 32k (k-quarter = blockIdx.y).
__global__ void __launch_bounds__(128, 4)
min_dist_kernel(const float* __restrict__ x, float* __restrict__ out) {
    extern __shared__ __align__(16) char smem[];
    const int tid = threadIdx.x, wr = tid >> 5, lane = tid & 31;
    const int g = lane >> 2, q = lane & 3;
    const int kq = blockIdx.y, n = blockIdx.z, wbase = blockIdx.x * WT;

    int* s_min = (int*)(smem + SM_MIN);

    float ds[32];
#pragma unroll
    for (int i = 0; i < 32; i++) ds[i] = 0.f;

    // ---- cp.async staging: band slice + B quarter + sqx slice -> buffer BUF ----
    // BUF is a template param so all smem destinations are compile-time immediates.
    auto stage = [&](int c, auto bufc) {
        constexpr int BOFF = decltype(bufc)::value * BUFSZ;
        uint32_t adst = smem_u32(smem) + BOFF + O_A;
        const char* asrc = (const char*)&g_band[n][c][0] + (size_t)wbase * APITCH;
#pragma unroll
        for (int i = 0; i < 5; i++) {            // 528 chunks, dense 1:1 copy
            int idx = tid + i * 128;
            if (idx < (AROWS * APITCH) / 16) cp16(adst + idx * 16, asrc + (size_t)idx * 16);
        }
        uint32_t bdst = smem_u32(smem) + BOFF + O_B;
        const char* bsrc = (const char*)&g_shb[c][(size_t)kq * 32 * PAD];
#pragma unroll
        for (int i = 0; i < 3; i++) {            // 288 chunks
            int idx = tid + i * 128;
            if (idx < (32 * PAD * 2) / 16) cp16(bdst + idx * 16, bsrc + (size_t)idx * 16);
        }
        if (tid < 32)
            cp16(smem_u32(smem) + BOFF + O_SQX + tid * 16,
                 (const char*)&g_sqx[n][c][wbase] + tid * 16);
        asm volatile("cp.async.commit_group;" ::: "memory");
    };

    // ---- per-channel compute: m32n32 warp tile, diagonal A sharing ----
    // cc seeded with (sqx+S)/2; B negated -> cc_final = t/2 - cross; d = sqrt2*sqrt(|cc|)
    auto compute = [&](auto bufc) {
        constexpr int BOFF = decltype(bufc)::value * BUFSZ;
        const float* sqx = (const float*)(smem + BOFF + O_SQX);
        uint32_t abase = smem_u32(smem) + BOFF + O_A
                       + (uint32_t)(wr * 32 + (lane & 15)) * APITCH + (lane >> 4) * 16;
        uint32_t bbase = smem_u32(smem) + BOFF + O_B
                       + (uint32_t)(lane & 15) * (PAD * 2) + (lane >> 4) * 16;

        uint32_t af[5][4];            // diagonal d = mi + kk, d in 0..4
#pragma unroll
        for (int d = 0; d < 5; d++)
            ldm4(af[d], abase + (uint32_t)d * 16 * APITCH);

        float th[2][2];               // 0.5*(sqx + S)
#pragma unroll
        for (int mi = 0; mi < 2; mi++) {
            th[mi][0] = fmaf(0.5f, sqx[wr * 32 + mi * 16 + g],     0.5f * (float)S_);
            th[mi][1] = fmaf(0.5f, sqx[wr * 32 + mi * 16 + g + 8], 0.5f * (float)S_);
        }

#pragma unroll
        for (int nt = 0; nt < 2; nt++) {
            uint32_t bf[4][4];
#pragma unroll
            for (int kk = 0; kk < 4; kk++)
                ldm4(bf[kk], bbase + (uint32_t)nt * 16 * (PAD * 2) + kk * 32);
            float cc[16];
#pragma unroll
            for (int mi = 0; mi < 2; mi++)
#pragma unroll
                for (int h = 0; h < 2; h++) {
                    cc[mi * 8 + h * 4 + 0] = th[mi][0];
                    cc[mi * 8 + h * 4 + 1] = th[mi][0];
                    cc[mi * 8 + h * 4 + 2] = th[mi][1];
                    cc[mi * 8 + h * 4 + 3] = th[mi][1];
                }
#pragma unroll
            for (int kk = 0; kk < 4; kk++)
#pragma unroll
                for (int mi = 0; mi < 2; mi++) {
                    mma_bf16(&cc[mi * 8],     af[mi + kk], bf[kk][0], bf[kk][2]);
                    mma_bf16(&cc[mi * 8 + 4], af[mi + kk], bf[kk][1], bf[kk][3]);
                }
#pragma unroll
            for (int e = 0; e < 16; e++) {
                float s = fast_sqrt(fabsf(cc[e]));
                ds[nt * 16 + e] = fmaf(SQRT2F, s, ds[nt * 16 + e]);
            }
        }
    };

    // ---- channel loop: partial unroll x2 (literal buf), ONE barrier per channel ----
    std::integral_constant<int, 0> B0;
    std::integral_constant<int, 1> B1;
    stage(0, B0);
    for (int cp = 0; cp < 4; cp++) {            // rolled: body 2x, buf compile-time
        const int c = cp * 2;
        // even channel (buf 0)
        asm volatile("cp.async.wait_group 0;" ::: "memory");
        __syncthreads();
        stage(c + 1, B1);
        compute(B0);
        // odd channel (buf 1)
        asm volatile("cp.async.wait_group 0;" ::: "memory");
        __syncthreads();
        if (c + 2 < C_) stage(c + 2, B0);
        compute(B1);
    }

    // ---- min over windows (32 cols for this k-quarter) ----
    __syncthreads();
    if (tid < 32) s_min[tid] = 0x7F800000;
    __syncthreads();

    bool v[2][2];
#pragma unroll
    for (int mi = 0; mi < 2; mi++)
#pragma unroll
        for (int hh = 0; hh < 2; hh++)
            v[mi][hh] = (wbase + wr * 32 + mi * 16 + g + hh * 8) < W_;

#pragma unroll
    for (int nt = 0; nt < 2; nt++)
#pragma unroll
        for (int h = 0; h < 2; h++)
#pragma unroll
            for (int j = 0; j < 2; j++) {
                float m = CUDART_INF_F;
#pragma unroll
                for (int mi = 0; mi < 2; mi++)
#pragma unroll
                    for (int hh = 0; hh < 2; hh++) {
                        float val = v[mi][hh] ? ds[nt * 16 + mi * 8 + h * 4 + hh * 2 + j]
                                              : CUDART_INF_F;
                        m = fminf(m, val);
                    }
#pragma unroll
                for (int o = 4; o < 32; o <<= 1) m = fminf(m, __shfl_xor_sync(0xffffffffu, m, o));
                if (g == 0) {
                    int col = nt * 16 + h * 8 + q * 2 + j;
                    atomicMin(&s_min[col], __float_as_int(m));
                }
            }
    __syncthreads();
    if (tid < 32) atomicMin((int*)&out[(size_t)n * K_ + kq * 32 + tid], s_min[tid]);
}

// ---------------- launch ----------------
extern "C" void kernel_launch(void* const* d_in, const int* in_sizes, int n_in,
                              void* d_out, int out_size) {
    const float* x  = (const float*)d_in[0];   // (64, 8, 2048)
    const float* sh = (const float*)d_in[1];   // (8, 128, 64)
    float* out = (float*)d_out;                // (64, 1, 128)

    cudaFuncSetAttribute(min_dist_kernel, cudaFuncAttributeMaxDynamicSharedMemorySize, SM_TOTAL);

    prep_kernel<<<576, 512>>>(x, sh, out);
    min_dist_kernel<<<dim3(NWT, 4, N_), 128, SM_TOTAL>>>(x, out);
}

// round 16
// speedup vs baseline: 1.2006x; 1.0475x over previous
#include <cuda_runtime.h>
#include <cuda_bf16.h>
#include <cstdint>
#include <math_constants.h>

#define N_  64
#define C_  8
#define L_  2048
#define S_  64
#define K_  128
#define W_  (L_ - S_ + 1)          /* 1985 */
#define WT  128                    /* windows per block */
#define NWT ((W_ + WT - 1) / WT)   /* 16 */
#define PAD 72                     /* B row pitch in bf16 (144B): conflict-free ldmatrix */
#define APITCH 48                  /* band pitch bytes, global AND smem (dense 1:1 copy) */
#define AROWS 176                  /* band rows staged per tile */
#define BROWS 2112                 /* global band rows per (n,c), zero-padded */
#define SQRT2F 1.41421356237f

// ---- dynamic smem (per buffer): band 8448 | B(32k) 4608 | sqx 512 ----
#define O_A      0
#define O_B      8448
#define O_SQX    13056
#define BUFSZ    13568
#define SM_MIN   27136             /* 32 int */
#define SM_TOTAL 27264

// ---------------- device scratch ----------------
__device__ __align__(16) __nv_bfloat16 g_shb[C_][K_ * PAD];            // NEGATED z-normed shapelets
__device__ __align__(16) __nv_bfloat16 g_band[N_][C_][BROWS * 24];     // Toeplitz band, pitch 48B
__device__ __align__(16) float         g_sqx[N_][C_][2048];            // window sum-of-squares

// ---------------- helpers ----------------
__device__ __forceinline__ uint32_t smem_u32(const void* p) {
    uint32_t a;
    asm("{ .reg .u64 t; cvta.to.shared.u64 t, %1; cvt.u32.u64 %0, t; }" : "=r"(a) : "l"(p));
    return a;
}
__device__ __forceinline__ float fast_sqrt(float x) {
    float r; asm("sqrt.approx.f32 %0, %1;" : "=f"(r) : "f"(x)); return r;
}
__device__ __forceinline__ void ldm4(uint32_t* r, uint32_t addr) {
    asm volatile("ldmatrix.sync.aligned.m8n8.x4.shared.b16 {%0,%1,%2,%3}, [%4];"
                 : "=r"(r[0]), "=r"(r[1]), "=r"(r[2]), "=r"(r[3]) : "r"(addr));
}
__device__ __forceinline__ void mma_bf16(float* c,
                                         const uint32_t* a, uint32_t b0, uint32_t b1) {
    asm volatile("mma.sync.aligned.m16n8k16.row.col.f32.bf16.bf16.f32 "
                 "{%0,%1,%2,%3}, {%4,%5,%6,%7}, {%8,%9}, {%0,%1,%2,%3};"
                 : "+f"(c[0]), "+f"(c[1]), "+f"(c[2]), "+f"(c[3])
                 : "r"(a[0]), "r"(a[1]), "r"(a[2]), "r"(a[3]), "r"(b0), "r"(b1));
}
__device__ __forceinline__ void cp16(uint32_t dst, const void* src) {
    asm volatile("cp.async.cg.shared.global [%0], [%1], 16;" :: "r"(dst), "l"(src));
}
__device__ __forceinline__ uint32_t bf2u(float a, float b) {
    __nv_bfloat162 v = __floats2bfloat162_rn(a, b);
    return *(uint32_t*)&v;
}

// ---------------- merged prep (576 blocks x 512 threads) ----------------
// blocks 0..511   : band + sqx for (n = b>>3, c = b&7)
// blocks 512..575 : shapelet z-norm (negated), c==0 also init out
__global__ void prep_kernel(const float* __restrict__ x, const float* __restrict__ sh,
                            float* __restrict__ out) {
    const int b = blockIdx.x, tid = threadIdx.x;
    if (b < 512) {
        const int n = b >> 3, c = b & 7;
        const int wid = tid >> 5, lane = tid & 31;
        __shared__ float sx[2304];                       // 2048 data + 256 zero pad
        __shared__ __nv_bfloat16 sxb[4][2176];           // shifted bf16 copies
        __shared__ float P[2052];                        // prefix of squares (2049 used)
        __shared__ float wsum[16];

        const float4* xr4 = (const float4*)(x + ((size_t)n * C_ + c) * L_);
        float4 a = xr4[tid];
        ((float4*)sx)[tid] = a;                          // 2048 floats
        if (tid < 64) ((float4*)sx)[512 + tid] = make_float4(0.f, 0.f, 0.f, 0.f);
        __syncthreads();

        // ---- 4 shifted bf16 copies: copy p element e = bf16(sx[e+p]) ----
        for (int i = tid; i < 544; i += 512) {           // elements 4i..4i+3 per copy
            float4 va = ((float4*)sx)[i];
            float4 vb = ((float4*)sx)[i + 1];
            float f[8] = { va.x, va.y, va.z, va.w, vb.x, vb.y, vb.z, vb.w };
#pragma unroll
            for (int p = 0; p < 4; p++) {
                uint2 v2 = make_uint2(bf2u(f[p], f[p + 1]), bf2u(f[p + 2], f[p + 3]));
                *(uint2*)&sxb[p][4 * i] = v2;            // 8B aligned
            }
        }

        // ---- prefix scan of squares ----
        float q0 = a.x * a.x;
        float q1 = q0 + a.y * a.y;
        float q2 = q1 + a.z * a.z;
        float q3 = q2 + a.w * a.w;
        float t3 = q3;
#pragma unroll
        for (int o = 1; o < 32; o <<= 1) {
            float u = __shfl_up_sync(0xffffffffu, t3, o);
            if (lane >= o) t3 += u;
        }
        if (lane == 31) wsum[wid] = t3;
        __syncthreads();
        if (tid == 0) {
            float acc = 0.f;
#pragma unroll
            for (int k = 0; k < 16; k++) { float t = wsum[k]; wsum[k] = acc; acc += t; }
        }
        __syncthreads();
        float base = wsum[wid] + (t3 - q3);              // exclusive prefix before 4*tid
        P[4 * tid]     = base;
        P[4 * tid + 1] = base + q0;
        P[4 * tid + 2] = base + q1;
        P[4 * tid + 3] = base + q2;
        if (tid == 511) P[2048] = base + q3;
        __syncthreads();

        // ---- band: chunk idx -> (row = idx>>1, h = idx&1); two LDS.64 + STG.128 ----
        char* band = (char*)&g_band[n][c][0];
#pragma unroll
        for (int i = 0; i < 9; i++) {
            int idx = tid + i * 512;
            if (idx < BROWS * 2) {
                int row = idx >> 1, h = idx & 1;
                int s = row + 8 * h;
                int p = s & 3;
                int e0 = s - p;                          // aligned mod 4; e0+7 <= 2126 < 2176
                uint2 lo = *(const uint2*)&sxb[p][e0];
                uint2 hi = *(const uint2*)&sxb[p][e0 + 4];
                uint4 v = make_uint4(lo.x, lo.y, hi.x, hi.y);
                *(uint4*)(band + (size_t)row * APITCH + h * 16) = v;
            }
        }

        // ---- sqx[w] = P[w+64] - P[w] ----
#pragma unroll
        for (int it = 0; it < 4; it++) {
            int w = tid + it * 512;
            int hi = w + 64; if (hi > 2048) hi = 2048;   // w >= 1985 is masked downstream
            g_sqx[n][c][w] = P[hi] - P[w];
        }
    } else {
        const int bb = b - 512;
        const int c = bb >> 3, kg = bb & 7;
        const int wid = tid >> 5, lane = tid & 31;
        const int k = kg * 16 + wid;
        const float* p = sh + ((size_t)c * K_ + k) * S_;

        float a = p[lane], bv = p[lane + 32];
        float s = a + bv;
#pragma unroll
        for (int o = 16; o > 0; o >>= 1) s += __shfl_xor_sync(0xffffffffu, s, o);
        float mu = s * (1.0f / S_);
        float da = a - mu, db = bv - mu;
        float v = da * da + db * db;
#pragma unroll
        for (int o = 16; o > 0; o >>= 1) v += __shfl_xor_sync(0xffffffffu, v, o);
        float inv = -rsqrtf(v * (1.0f / S_));    // NEGATED z-norm

        __nv_bfloat16* row = &g_shb[c][(size_t)k * PAD];
        row[lane]      = __float2bfloat16_rn(da * inv);
        row[lane + 32] = __float2bfloat16_rn(db * inv);

        if (c == 0) {
            int i = kg * 512 + tid;
            out[i] = CUDART_INF_F;
            out[i + 4096] = CUDART_INF_F;
        }
    }
}

// ---------------- main kernel (R15, unchanged) ----------------
// 128 threads (4 warps). CTA tile: 128w x 32k (k-quarter = blockIdx.y).
__global__ void __launch_bounds__(128, 4)
min_dist_kernel(const float* __restrict__ x, float* __restrict__ out) {
    extern __shared__ __align__(16) char smem[];
    const int tid = threadIdx.x, wr = tid >> 5, lane = tid & 31;
    const int g = lane >> 2, q = lane & 3;
    const int kq = blockIdx.y, n = blockIdx.z, wbase = blockIdx.x * WT;

    int* s_min = (int*)(smem + SM_MIN);

    float ds[32];
#pragma unroll
    for (int i = 0; i < 32; i++) ds[i] = 0.f;

    auto stage = [&](int c, auto bufc) {
        constexpr int BOFF = decltype(bufc)::value * BUFSZ;
        uint32_t adst = smem_u32(smem) + BOFF + O_A;
        const char* asrc = (const char*)&g_band[n][c][0] + (size_t)wbase * APITCH;
#pragma unroll
        for (int i = 0; i < 5; i++) {            // 528 chunks, dense 1:1 copy
            int idx = tid + i * 128;
            if (idx < (AROWS * APITCH) / 16) cp16(adst + idx * 16, asrc + (size_t)idx * 16);
        }
        uint32_t bdst = smem_u32(smem) + BOFF + O_B;
        const char* bsrc = (const char*)&g_shb[c][(size_t)kq * 32 * PAD];
#pragma unroll
        for (int i = 0; i < 3; i++) {            // 288 chunks
            int idx = tid + i * 128;
            if (idx < (32 * PAD * 2) / 16) cp16(bdst + idx * 16, bsrc + (size_t)idx * 16);
        }
        if (tid < 32)
            cp16(smem_u32(smem) + BOFF + O_SQX + tid * 16,
                 (const char*)&g_sqx[n][c][wbase] + tid * 16);
        asm volatile("cp.async.commit_group;" ::: "memory");
    };

    auto compute = [&](auto bufc) {
        constexpr int BOFF = decltype(bufc)::value * BUFSZ;
        const float* sqx = (const float*)(smem + BOFF + O_SQX);
        uint32_t abase = smem_u32(smem) + BOFF + O_A
                       + (uint32_t)(wr * 32 + (lane & 15)) * APITCH + (lane >> 4) * 16;
        uint32_t bbase = smem_u32(smem) + BOFF + O_B
                       + (uint32_t)(lane & 15) * (PAD * 2) + (lane >> 4) * 16;

        uint32_t af[5][4];            // diagonal d = mi + kk, d in 0..4
#pragma unroll
        for (int d = 0; d < 5; d++)
            ldm4(af[d], abase + (uint32_t)d * 16 * APITCH);

        float th[2][2];               // 0.5*(sqx + S)
#pragma unroll
        for (int mi = 0; mi < 2; mi++) {
            th[mi][0] = fmaf(0.5f, sqx[wr * 32 + mi * 16 + g],     0.5f * (float)S_);
            th[mi][1] = fmaf(0.5f, sqx[wr * 32 + mi * 16 + g + 8], 0.5f * (float)S_);
        }

#pragma unroll
        for (int nt = 0; nt < 2; nt++) {
            uint32_t bf[4][4];
#pragma unroll
            for (int kk = 0; kk < 4; kk++)
                ldm4(bf[kk], bbase + (uint32_t)nt * 16 * (PAD * 2) + kk * 32);
            float cc[16];
#pragma unroll
            for (int mi = 0; mi < 2; mi++)
#pragma unroll
                for (int h = 0; h < 2; h++) {
                    cc[mi * 8 + h * 4 + 0] = th[mi][0];
                    cc[mi * 8 + h * 4 + 1] = th[mi][0];
                    cc[mi * 8 + h * 4 + 2] = th[mi][1];
                    cc[mi * 8 + h * 4 + 3] = th[mi][1];
                }
#pragma unroll
            for (int kk = 0; kk < 4; kk++)
#pragma unroll
                for (int mi = 0; mi < 2; mi++) {
                    mma_bf16(&cc[mi * 8],     af[mi + kk], bf[kk][0], bf[kk][2]);
                    mma_bf16(&cc[mi * 8 + 4], af[mi + kk], bf[kk][1], bf[kk][3]);
                }
#pragma unroll
            for (int e = 0; e < 16; e++) {
                float s = fast_sqrt(fabsf(cc[e]));
                ds[nt * 16 + e] = fmaf(SQRT2F, s, ds[nt * 16 + e]);
            }
        }
    };

    // ---- channel loop: partial unroll x2 (literal buf), ONE barrier per channel ----
    std::integral_constant<int, 0> B0;
    std::integral_constant<int, 1> B1;
    stage(0, B0);
    for (int cp = 0; cp < 4; cp++) {
        const int c = cp * 2;
        asm volatile("cp.async.wait_group 0;" ::: "memory");
        __syncthreads();
        stage(c + 1, B1);
        compute(B0);
        asm volatile("cp.async.wait_group 0;" ::: "memory");
        __syncthreads();
        if (c + 2 < C_) stage(c + 2, B0);
        compute(B1);
    }

    // ---- min over windows (32 cols for this k-quarter) ----
    __syncthreads();
    if (tid < 32) s_min[tid] = 0x7F800000;
    __syncthreads();

    bool v[2][2];
#pragma unroll
    for (int mi = 0; mi < 2; mi++)
#pragma unroll
        for (int hh = 0; hh < 2; hh++)
            v[mi][hh] = (wbase + wr * 32 + mi * 16 + g + hh * 8) < W_;

#pragma unroll
    for (int nt = 0; nt < 2; nt++)
#pragma unroll
        for (int h = 0; h < 2; h++)
#pragma unroll
            for (int j = 0; j < 2; j++) {
                float m = CUDART_INF_F;
#pragma unroll
                for (int mi = 0; mi < 2; mi++)
#pragma unroll
                    for (int hh = 0; hh < 2; hh++) {
                        float val = v[mi][hh] ? ds[nt * 16 + mi * 8 + h * 4 + hh * 2 + j]
                                              : CUDART_INF_F;
                        m = fminf(m, val);
                    }
#pragma unroll
                for (int o = 4; o < 32; o <<= 1) m = fminf(m, __shfl_xor_sync(0xffffffffu, m, o));
                if (g == 0) {
                    int col = nt * 16 + h * 8 + q * 2 + j;
                    atomicMin(&s_min[col], __float_as_int(m));
                }
            }
    __syncthreads();
    if (tid < 32) atomicMin((int*)&out[(size_t)n * K_ + kq * 32 + tid], s_min[tid]);
}

// ---------------- launch ----------------
extern "C" void kernel_launch(void* const* d_in, const int* in_sizes, int n_in,
                              void* d_out, int out_size) {
    const float* x  = (const float*)d_in[0];   // (64, 8, 2048)
    const float* sh = (const float*)d_in[1];   // (8, 128, 64)
    float* out = (float*)d_out;                // (64, 1, 128)

    cudaFuncSetAttribute(min_dist_kernel, cudaFuncAttributeMaxDynamicSharedMemorySize, SM_TOTAL);

    prep_kernel<<<576, 512>>>(x, sh, out);
    min_dist_kernel<<<dim3(NWT, 4, N_), 128, SM_TOTAL>>>(x, out);
}